// round 14
// baseline (speedup 1.0000x reference)
#include <cuda_runtime.h>
#include <cuda_fp16.h>

#define N_USER 100000
#define N_ITEM 20000
#define N_NODES 120000
#define N_EDGES 2000000
#define EMB 64
#define V4 8        // uint4 (8-half / 16B) chunks per 64-dim fp16 row
#define F4 16       // float4 chunks per 64-dim fp32 row
#define NB_SCAN 469 // cdiv(N_NODES, 256)

// ---- static scratch (no allocations allowed) ----
__device__ __half g_y0[N_NODES * EMB];   // dis ⊙ x0
__device__ __half g_y1[N_NODES * EMB];   // dis ⊙ x1
__device__ __half g_ho[N_NODES * EMB];   // combined output embedding
__device__ int    g_deg[N_NODES];        // zero-initialized; re-zeroed by k_dot each call
__device__ int    g_rank[N_EDGES];       // edge's arrival rank within its dst
__device__ int    g_rowptr[N_NODES + 1];
__device__ int    g_bsum[512];
__device__ int    g_boff[512];           // exclusive prefix of g_bsum
__device__ int    g_arrive;              // scan_a completion ticket (self-resetting)
__device__ float  g_dis[N_NODES];        // 1/sqrt(deg) (0 if deg=0)
__device__ float  g_sqd[N_NODES];        // sqrt(deg)   (0 if deg=0)
__device__ uint2  g_adje[N_EDGES];       // {src, eid} grouped by dst (gather + dot)

static inline int cdiv(int a, int b) { return (a + b - 1) / b; }

__device__ __forceinline__ void h8_acc(float4* accA, float4* accB, uint4 u) {
    float2 f0 = __half22float2(*reinterpret_cast<__half2*>(&u.x));
    float2 f1 = __half22float2(*reinterpret_cast<__half2*>(&u.y));
    float2 f2 = __half22float2(*reinterpret_cast<__half2*>(&u.z));
    float2 f3 = __half22float2(*reinterpret_cast<__half2*>(&u.w));
    accA->x += f0.x; accA->y += f0.y; accA->z += f1.x; accA->w += f1.y;
    accB->x += f2.x; accB->y += f2.y; accB->z += f3.x; accB->w += f3.y;
}

__device__ __forceinline__ void h8_mul_acc(float4* accA, float4* accB, uint4 u, float s) {
    float2 f0 = __half22float2(*reinterpret_cast<__half2*>(&u.x));
    float2 f1 = __half22float2(*reinterpret_cast<__half2*>(&u.y));
    float2 f2 = __half22float2(*reinterpret_cast<__half2*>(&u.z));
    float2 f3 = __half22float2(*reinterpret_cast<__half2*>(&u.w));
    accA->x += f0.x * s; accA->y += f0.y * s; accA->z += f1.x * s; accA->w += f1.y * s;
    accB->x += f2.x * s; accB->y += f2.y * s; accB->z += f3.x * s; accB->w += f3.y * s;
}

__device__ __forceinline__ uint4 pack8(float4 a, float4 b) {
    __half2 p0 = __floats2half2_rn(a.x, a.y);
    __half2 p1 = __floats2half2_rn(a.z, a.w);
    __half2 p2 = __floats2half2_rn(b.x, b.y);
    __half2 p3 = __floats2half2_rn(b.z, b.w);
    return make_uint4(*reinterpret_cast<unsigned*>(&p0), *reinterpret_cast<unsigned*>(&p1),
                      *reinterpret_cast<unsigned*>(&p2), *reinterpret_cast<unsigned*>(&p3));
}

__device__ __forceinline__ float4 scale4(float4 v, float s) {
    return make_float4(v.x * s, v.y * s, v.z * s, v.w * s);
}

// compute the x0 chunk (2 float4s) for node n, chunk q, directly from inputs
__device__ __forceinline__ void x0_chunk(int n, int q,
                                         const float4* __restrict__ user_emb,
                                         const float4* __restrict__ item_emb,
                                         const int*    __restrict__ tag,
                                         const int*    __restrict__ testid,
                                         const int*    __restrict__ bigcat,
                                         const float4* __restrict__ tag_emb,
                                         const float4* __restrict__ testid_emb,
                                         const float4* __restrict__ bigcat_emb,
                                         float4* va, float4* vb) {
    if (n < N_USER) {
        *va = user_emb[n * F4 + 2 * q];
        *vb = user_emb[n * F4 + 2 * q + 1];
    } else {
        int i = n - N_USER;
        int tg = tag[i] * F4, ts = testid[i] * F4, bc = bigcat[i] * F4;
        float4 a0 = item_emb[i * F4 + 2 * q],     a1 = item_emb[i * F4 + 2 * q + 1];
        float4 b0 = tag_emb[tg + 2 * q],          b1 = tag_emb[tg + 2 * q + 1];
        float4 c0 = testid_emb[ts + 2 * q],       c1 = testid_emb[ts + 2 * q + 1];
        float4 d0 = bigcat_emb[bc + 2 * q],       d1 = bigcat_emb[bc + 2 * q + 1];
        *va = make_float4((a0.x + b0.x + c0.x + d0.x) * 0.25f,
                          (a0.y + b0.y + c0.y + d0.y) * 0.25f,
                          (a0.z + b0.z + c0.z + d0.z) * 0.25f,
                          (a0.w + b0.w + c0.w + d0.w) * 0.25f);
        *vb = make_float4((a1.x + b1.x + c1.x + d1.x) * 0.25f,
                          (a1.y + b1.y + c1.y + d1.y) * 0.25f,
                          (a1.z + b1.z + c1.z + d1.z) * 0.25f,
                          (a1.w + b1.w + c1.w + d1.w) * 0.25f);
    }
}

// ---------------------------------------------------------------------------
// degree count + per-edge rank (slot within destination) in one pass
__global__ void k_deg_rank(const int* __restrict__ col) {
    int e = blockIdx.x * blockDim.x + threadIdx.x;
    if (e < N_EDGES) g_rank[e] = atomicAdd(&g_deg[col[e]], 1);
}

// ---- block sums of deg + rsqrt/sqrt; LAST block computes g_boff prefix ----
__global__ void k_scan_a_dis() {
    __shared__ int sh[256];
    int i = blockIdx.x * 256 + threadIdx.x;
    int d = (i < N_NODES) ? g_deg[i] : 0;
    if (i < N_NODES) {
        float fd = (float)d;
        g_dis[i] = (d > 0) ? rsqrtf(fd) : 0.0f;
        g_sqd[i] = (d > 0) ? sqrtf(fd) : 0.0f;
    }
    sh[threadIdx.x] = d;
    __syncthreads();
    for (int s = 128; s > 0; s >>= 1) {
        if (threadIdx.x < s) sh[threadIdx.x] += sh[threadIdx.x + s];
        __syncthreads();
    }
    __shared__ int lastflag;
    if (threadIdx.x == 0) {
        g_bsum[blockIdx.x] = sh[0];
        __threadfence();
        lastflag = (atomicAdd(&g_arrive, 1) == gridDim.x - 1);
    }
    __syncthreads();
    if (!lastflag) return;
    // last block: exclusive prefix of g_bsum[0..NB_SCAN) into g_boff (ping-pong scan)
    __shared__ int pa[512], pb[512];
    int t = threadIdx.x;
    pa[t]       = (t < NB_SCAN) ? g_bsum[t] : 0;
    pa[t + 256] = (t + 256 < NB_SCAN) ? g_bsum[t + 256] : 0;
    __syncthreads();
    int *src = pa, *dst = pb;
    for (int off = 1; off < 512; off <<= 1) {
        dst[t]       = src[t]       + ((t >= off)       ? src[t - off]       : 0);
        dst[t + 256] = src[t + 256] + ((t + 256 >= off) ? src[t + 256 - off] : 0);
        __syncthreads();
        int* tmp = src; src = dst; dst = tmp;
    }
    if (t < NB_SCAN)       g_boff[t]       = (t == 0) ? 0 : src[t - 1];
    if (t + 256 < NB_SCAN) g_boff[t + 256] = src[t + 255];
    if (t == 0) g_arrive = 0;   // reset ticket for next call
}

// ---- y0 = dis*x0 (fp16) with rowptr scan fused into the first NB_SCAN blocks
__global__ void k_x0_scan(const float4* __restrict__ user_emb,
                          const float4* __restrict__ item_emb,
                          const int*    __restrict__ tag,
                          const int*    __restrict__ testid,
                          const int*    __restrict__ bigcat,
                          const float4* __restrict__ tag_emb,
                          const float4* __restrict__ testid_emb,
                          const float4* __restrict__ bigcat_emb) {
    // part 1: rowptr (exclusive, N+1) for blocks < NB_SCAN
    if (blockIdx.x < NB_SCAN) {
        __shared__ int sh[256];
        int i = blockIdx.x * 256 + threadIdx.x;
        int v = (i < N_NODES) ? g_deg[i] : 0;
        sh[threadIdx.x] = v;
        __syncthreads();
        for (int off = 1; off < 256; off <<= 1) {
            int x = (threadIdx.x >= off) ? sh[threadIdx.x - off] : 0;
            __syncthreads();
            sh[threadIdx.x] += x;
            __syncthreads();
        }
        if (i < N_NODES) {
            g_rowptr[i + 1] = g_boff[blockIdx.x] + sh[threadIdx.x];
            if (i == 0) g_rowptr[0] = 0;
        }
    }
    // part 2: y0 features (all blocks)
    int t = blockIdx.x * blockDim.x + threadIdx.x;
    if (t >= N_NODES * V4) return;
    int n = t >> 3, q = t & 7;
    float4 va, vb;
    x0_chunk(n, q, user_emb, item_emb, tag, testid, bigcat,
             tag_emb, testid_emb, bigcat_emb, &va, &vb);
    float dn = g_dis[n];
    reinterpret_cast<uint4*>(g_y0)[t] = pack8(scale4(va, dn), scale4(vb, dn));
}

// ---- CSR fill: atomic-free; slot = rowptr[dst] + rank ----
__global__ void k_fill(const int* __restrict__ row, const int* __restrict__ col) {
    int e = blockIdx.x * blockDim.x + threadIdx.x;
    if (e >= N_EDGES) return;
    int r = row[e], c = col[e];
    int pos = __ldg(&g_rowptr[c]) + g_rank[e];
    g_adje[pos] = make_uint2((unsigned)r, (unsigned)e);
}

// ---- layer 1: acc = Σ y0[src]; y1 = dis²*acc (x1 recovered as y1*sqd later) --
__global__ void k_gather1() {
    int t = blockIdx.x * blockDim.x + threadIdx.x;
    if (t >= N_NODES * V4) return;
    int n = t >> 3, q = t & 7;
    int start = g_rowptr[n];
    int end = g_rowptr[n + 1];
    const uint4* y0 = reinterpret_cast<const uint4*>(g_y0);
    float4 accA = make_float4(0.f, 0.f, 0.f, 0.f);
    float4 accB = make_float4(0.f, 0.f, 0.f, 0.f);
    #pragma unroll 4
    for (int i = start; i < end; i++) {
        unsigned src = __ldg(&g_adje[i]).x;
        h8_acc(&accA, &accB, __ldg(&y0[src * V4 + q]));
    }
    float dn = g_dis[n];
    float d2 = dn * dn;
    reinterpret_cast<uint4*>(g_y1)[t] = pack8(scale4(accA, d2), scale4(accB, d2));
}

// ---- layer 2 + combine: ho = a0*(y0*sqd) + a1*(y1*sqd) + a2*dis*(Σ y1[src]) --
// deg-0 nodes: all propagation terms zero; x0 recomputed inline from inputs.
__global__ void k_gather_combine(const float* __restrict__ alpha,
                                 const float4* __restrict__ user_emb,
                                 const float4* __restrict__ item_emb,
                                 const int*    __restrict__ tag,
                                 const int*    __restrict__ testid,
                                 const int*    __restrict__ bigcat,
                                 const float4* __restrict__ tag_emb,
                                 const float4* __restrict__ testid_emb,
                                 const float4* __restrict__ bigcat_emb) {
    int t = blockIdx.x * blockDim.x + threadIdx.x;
    if (t >= N_NODES * V4) return;
    int n = t >> 3, q = t & 7;
    int start = g_rowptr[n];
    int end = g_rowptr[n + 1];
    float a0 = alpha[0];
    if (start == end) {                      // rare: isolated node, ho = a0*x0
        float4 va, vb;
        x0_chunk(n, q, user_emb, item_emb, tag, testid, bigcat,
                 tag_emb, testid_emb, bigcat_emb, &va, &vb);
        reinterpret_cast<uint4*>(g_ho)[t] = pack8(scale4(va, a0), scale4(vb, a0));
        return;
    }
    const uint4* y1 = reinterpret_cast<const uint4*>(g_y1);
    float4 accA = make_float4(0.f, 0.f, 0.f, 0.f);
    float4 accB = make_float4(0.f, 0.f, 0.f, 0.f);
    #pragma unroll 4
    for (int i = start; i < end; i++) {
        unsigned src = __ldg(&g_adje[i]).x;
        h8_acc(&accA, &accB, __ldg(&y1[src * V4 + q]));
    }
    float sq = g_sqd[n];
    float a0s = a0 * sq, a1s = alpha[1] * sq, a2d = alpha[2] * g_dis[n];
    accA = scale4(accA, a2d);
    accB = scale4(accB, a2d);
    h8_mul_acc(&accA, &accB, reinterpret_cast<const uint4*>(g_y0)[t], a0s); // x0 = y0*sqd
    h8_mul_acc(&accA, &accB, y1[t], a1s);                                   // x1 = y1*sqd
    reinterpret_cast<uint4*>(g_ho)[t] = pack8(accA, accB);
}

// ---- per-edge dots in CSR order (8-lane groups); re-zeros deg for next call --
__global__ void k_dot_csr(float* __restrict__ out) {
    int t = blockIdx.x * blockDim.x + threadIdx.x;
    if (t >= N_NODES * V4) return;
    int n = t >> 3, q = t & 7;
    int start = g_rowptr[n];
    int end = g_rowptr[n + 1];
    if (q == 0) g_deg[n] = 0;                    // maintain zero-invariant
    if (start == end) return;
    unsigned gmask = 0xFFu << (threadIdx.x & 24);
    const uint4* h = reinterpret_cast<const uint4*>(g_ho);
    uint4 uc = h[n * V4 + q];                    // dst row chunk, loop-invariant
    float2 c0 = __half22float2(*reinterpret_cast<__half2*>(&uc.x));
    float2 c1 = __half22float2(*reinterpret_cast<__half2*>(&uc.y));
    float2 c2 = __half22float2(*reinterpret_cast<__half2*>(&uc.z));
    float2 c3 = __half22float2(*reinterpret_cast<__half2*>(&uc.w));
    #pragma unroll 2
    for (int i = start; i < end; i++) {
        uint2 a = __ldg(&g_adje[i]);             // {src, eid}
        uint4 ua = __ldg(&h[a.x * V4 + q]);
        float2 s0 = __half22float2(*reinterpret_cast<__half2*>(&ua.x));
        float2 s1 = __half22float2(*reinterpret_cast<__half2*>(&ua.y));
        float2 s2 = __half22float2(*reinterpret_cast<__half2*>(&ua.z));
        float2 s3 = __half22float2(*reinterpret_cast<__half2*>(&ua.w));
        float s = s0.x * c0.x + s0.y * c0.y + s1.x * c1.x + s1.y * c1.y
                + s2.x * c2.x + s2.y * c2.y + s3.x * c3.x + s3.y * c3.y;
        s += __shfl_xor_sync(gmask, s, 4);
        s += __shfl_xor_sync(gmask, s, 2);
        s += __shfl_xor_sync(gmask, s, 1);
        if (q == 0) out[a.y] = s;
    }
}

// ---------------------------------------------------------------------------
extern "C" void kernel_launch(void* const* d_in, const int* in_sizes, int n_in,
                              void* d_out, int out_size) {
    const int*    edge_index = (const int*)d_in[0];       // [2, E]
    const int*    item_tag   = (const int*)d_in[1];
    const int*    item_testid= (const int*)d_in[2];
    const int*    item_bigcat= (const int*)d_in[3];
    const float4* user_emb   = (const float4*)d_in[4];
    const float4* item_emb   = (const float4*)d_in[5];
    const float4* tag_emb    = (const float4*)d_in[6];
    const float4* testid_emb = (const float4*)d_in[7];
    const float4* bigcat_emb = (const float4*)d_in[8];
    const float*  alpha      = (const float*)d_in[9];
    float* out = (float*)d_out;

    const int* row = edge_index;
    const int* col = edge_index + N_EDGES;
    const int B = 256;

    // degree+rank (deg pre-zeroed by static init / previous k_dot_csr)
    k_deg_rank<<<cdiv(N_EDGES, B), B>>>(col);
    k_scan_a_dis<<<NB_SCAN, 256>>>();
    // y0 features with the rowptr scan fused into the first NB_SCAN blocks
    k_x0_scan<<<cdiv(N_NODES * V4, B), B>>>(user_emb, item_emb, item_tag, item_testid,
                                            item_bigcat, tag_emb, testid_emb, bigcat_emb);
    k_fill<<<cdiv(N_EDGES, B), B>>>(row, col);

    // 2 pull layers (pre-scaled rows; second layer fused with combine)
    k_gather1<<<cdiv(N_NODES * V4, B), B>>>();
    k_gather_combine<<<cdiv(N_NODES * V4, B), B>>>(alpha, user_emb, item_emb,
                                                   item_tag, item_testid, item_bigcat,
                                                   tag_emb, testid_emb, bigcat_emb);

    // per-edge dots via CSR traversal (also re-zeros deg)
    k_dot_csr<<<cdiv(N_NODES * V4, B), B>>>(out);
}

// round 15
// speedup vs baseline: 1.0239x; 1.0239x over previous
#include <cuda_runtime.h>
#include <cuda_fp16.h>

#define N_USER 100000
#define N_ITEM 20000
#define N_NODES 120000
#define N_EDGES 2000000
#define EMB 64
#define V4 8        // uint4 (8-half / 16B) chunks per 64-dim fp16 row
#define F4 16       // float4 chunks per 64-dim fp32 row
#define NB_SCAN 469 // cdiv(N_NODES, 256)

// ---- static scratch (no allocations allowed) ----
__device__ __half g_x0h[N_NODES * EMB];  // x0 (fp16)
__device__ __half g_y0[N_NODES * EMB];   // dis ⊙ x0
__device__ __half g_y1[N_NODES * EMB];   // dis ⊙ x1
__device__ __half g_ho[N_NODES * EMB];   // combined output embedding
__device__ int    g_deg[N_NODES];        // zero-initialized; re-zeroed by k_dot each call
__device__ int    g_rank[N_EDGES];       // edge's arrival rank within its dst
__device__ int    g_rowptr[N_NODES + 1];
__device__ int    g_bsum[512];
__device__ int    g_boff[512];           // exclusive prefix of g_bsum
__device__ int    g_arrive;              // scan_a completion ticket (self-resetting)
__device__ float  g_dis[N_NODES];        // 1/sqrt(deg) (0 if deg=0)
__device__ float  g_sqd[N_NODES];        // sqrt(deg)   (0 if deg=0)
__device__ uint2  g_adje[N_EDGES];       // {src, eid} grouped by dst (gather + dot)

static inline int cdiv(int a, int b) { return (a + b - 1) / b; }

__device__ __forceinline__ void h8_acc(float4* accA, float4* accB, uint4 u) {
    float2 f0 = __half22float2(*reinterpret_cast<__half2*>(&u.x));
    float2 f1 = __half22float2(*reinterpret_cast<__half2*>(&u.y));
    float2 f2 = __half22float2(*reinterpret_cast<__half2*>(&u.z));
    float2 f3 = __half22float2(*reinterpret_cast<__half2*>(&u.w));
    accA->x += f0.x; accA->y += f0.y; accA->z += f1.x; accA->w += f1.y;
    accB->x += f2.x; accB->y += f2.y; accB->z += f3.x; accB->w += f3.y;
}

__device__ __forceinline__ void h8_mul_acc(float4* accA, float4* accB, uint4 u, float s) {
    float2 f0 = __half22float2(*reinterpret_cast<__half2*>(&u.x));
    float2 f1 = __half22float2(*reinterpret_cast<__half2*>(&u.y));
    float2 f2 = __half22float2(*reinterpret_cast<__half2*>(&u.z));
    float2 f3 = __half22float2(*reinterpret_cast<__half2*>(&u.w));
    accA->x += f0.x * s; accA->y += f0.y * s; accA->z += f1.x * s; accA->w += f1.y * s;
    accB->x += f2.x * s; accB->y += f2.y * s; accB->z += f3.x * s; accB->w += f3.y * s;
}

__device__ __forceinline__ uint4 pack8(float4 a, float4 b) {
    __half2 p0 = __floats2half2_rn(a.x, a.y);
    __half2 p1 = __floats2half2_rn(a.z, a.w);
    __half2 p2 = __floats2half2_rn(b.x, b.y);
    __half2 p3 = __floats2half2_rn(b.z, b.w);
    return make_uint4(*reinterpret_cast<unsigned*>(&p0), *reinterpret_cast<unsigned*>(&p1),
                      *reinterpret_cast<unsigned*>(&p2), *reinterpret_cast<unsigned*>(&p3));
}

__device__ __forceinline__ float4 scale4(float4 v, float s) {
    return make_float4(v.x * s, v.y * s, v.z * s, v.w * s);
}

// ---------------------------------------------------------------------------
// degree count + per-edge rank (slot within destination) in one pass
__global__ void k_deg_rank(const int* __restrict__ col) {
    int e = blockIdx.x * blockDim.x + threadIdx.x;
    if (e < N_EDGES) g_rank[e] = atomicAdd(&g_deg[col[e]], 1);
}

// ---- block sums of deg + rsqrt/sqrt; LAST block computes g_boff prefix ----
__global__ void k_scan_a_dis() {
    __shared__ int sh[256];
    int i = blockIdx.x * 256 + threadIdx.x;
    int d = (i < N_NODES) ? g_deg[i] : 0;
    if (i < N_NODES) {
        float fd = (float)d;
        g_dis[i] = (d > 0) ? rsqrtf(fd) : 0.0f;
        g_sqd[i] = (d > 0) ? sqrtf(fd) : 0.0f;
    }
    sh[threadIdx.x] = d;
    __syncthreads();
    for (int s = 128; s > 0; s >>= 1) {
        if (threadIdx.x < s) sh[threadIdx.x] += sh[threadIdx.x + s];
        __syncthreads();
    }
    __shared__ int lastflag;
    if (threadIdx.x == 0) {
        g_bsum[blockIdx.x] = sh[0];
        __threadfence();
        lastflag = (atomicAdd(&g_arrive, 1) == gridDim.x - 1);
    }
    __syncthreads();
    if (!lastflag) return;
    // last block: exclusive prefix of g_bsum[0..NB_SCAN) into g_boff (ping-pong scan)
    __shared__ int pa[512], pb[512];
    int t = threadIdx.x;
    pa[t]       = (t < NB_SCAN) ? g_bsum[t] : 0;
    pa[t + 256] = (t + 256 < NB_SCAN) ? g_bsum[t + 256] : 0;
    __syncthreads();
    int *src = pa, *dst = pb;
    for (int off = 1; off < 512; off <<= 1) {
        dst[t]       = src[t]       + ((t >= off)       ? src[t - off]       : 0);
        dst[t + 256] = src[t + 256] + ((t + 256 >= off) ? src[t + 256 - off] : 0);
        __syncthreads();
        int* tmp = src; src = dst; dst = tmp;
    }
    if (t < NB_SCAN)       g_boff[t]       = (t == 0) ? 0 : src[t - 1];
    if (t + 256 < NB_SCAN) g_boff[t + 256] = src[t + 255];
    if (t == 0) g_arrive = 0;   // reset ticket for next call
}

// ---- x0 (fp16 + y0 = dis*x0) with rowptr scan fused into the first NB_SCAN blocks
__global__ void k_x0_scan(const float4* __restrict__ user_emb,
                          const float4* __restrict__ item_emb,
                          const int*    __restrict__ tag,
                          const int*    __restrict__ testid,
                          const int*    __restrict__ bigcat,
                          const float4* __restrict__ tag_emb,
                          const float4* __restrict__ testid_emb,
                          const float4* __restrict__ bigcat_emb) {
    // part 1: rowptr (exclusive, N+1) for blocks < NB_SCAN
    if (blockIdx.x < NB_SCAN) {
        __shared__ int sh[256];
        int i = blockIdx.x * 256 + threadIdx.x;
        int v = (i < N_NODES) ? g_deg[i] : 0;
        sh[threadIdx.x] = v;
        __syncthreads();
        for (int off = 1; off < 256; off <<= 1) {
            int x = (threadIdx.x >= off) ? sh[threadIdx.x - off] : 0;
            __syncthreads();
            sh[threadIdx.x] += x;
            __syncthreads();
        }
        if (i < N_NODES) {
            g_rowptr[i + 1] = g_boff[blockIdx.x] + sh[threadIdx.x];
            if (i == 0) g_rowptr[0] = 0;
        }
    }
    // part 2: x0 features (all blocks)
    int t = blockIdx.x * blockDim.x + threadIdx.x;
    if (t >= N_NODES * V4) return;
    int n = t >> 3, q = t & 7;
    float4 va, vb;
    if (n < N_USER) {
        va = user_emb[n * F4 + 2 * q];
        vb = user_emb[n * F4 + 2 * q + 1];
    } else {
        int i = n - N_USER;
        int tg = tag[i] * F4, ts = testid[i] * F4, bc = bigcat[i] * F4;
        float4 a0 = item_emb[i * F4 + 2 * q],     a1 = item_emb[i * F4 + 2 * q + 1];
        float4 b0 = tag_emb[tg + 2 * q],          b1 = tag_emb[tg + 2 * q + 1];
        float4 c0 = testid_emb[ts + 2 * q],       c1 = testid_emb[ts + 2 * q + 1];
        float4 d0 = bigcat_emb[bc + 2 * q],       d1 = bigcat_emb[bc + 2 * q + 1];
        va = make_float4((a0.x + b0.x + c0.x + d0.x) * 0.25f,
                         (a0.y + b0.y + c0.y + d0.y) * 0.25f,
                         (a0.z + b0.z + c0.z + d0.z) * 0.25f,
                         (a0.w + b0.w + c0.w + d0.w) * 0.25f);
        vb = make_float4((a1.x + b1.x + c1.x + d1.x) * 0.25f,
                         (a1.y + b1.y + c1.y + d1.y) * 0.25f,
                         (a1.z + b1.z + c1.z + d1.z) * 0.25f,
                         (a1.w + b1.w + c1.w + d1.w) * 0.25f);
    }
    float dn = g_dis[n];
    reinterpret_cast<uint4*>(g_x0h)[t] = pack8(va, vb);
    reinterpret_cast<uint4*>(g_y0)[t]  = pack8(scale4(va, dn), scale4(vb, dn));
}

// ---- CSR fill: atomic-free; slot = rowptr[dst] + rank ----
__global__ void k_fill(const int* __restrict__ row, const int* __restrict__ col) {
    int e = blockIdx.x * blockDim.x + threadIdx.x;
    if (e >= N_EDGES) return;
    int r = row[e], c = col[e];
    int pos = __ldg(&g_rowptr[c]) + g_rank[e];
    g_adje[pos] = make_uint2((unsigned)r, (unsigned)e);
}

// ---- layer 1: acc = Σ y0[src]; y1 = dis²*acc (x1 recovered as y1*sqd later) --
__global__ void k_gather1() {
    int t = blockIdx.x * blockDim.x + threadIdx.x;
    if (t >= N_NODES * V4) return;
    int n = t >> 3, q = t & 7;
    int start = g_rowptr[n];
    int end = g_rowptr[n + 1];
    const uint4* y0 = reinterpret_cast<const uint4*>(g_y0);
    float4 accA = make_float4(0.f, 0.f, 0.f, 0.f);
    float4 accB = make_float4(0.f, 0.f, 0.f, 0.f);
    #pragma unroll 4
    for (int i = start; i < end; i++) {
        unsigned src = __ldg(&g_adje[i]).x;
        h8_acc(&accA, &accB, __ldg(&y0[src * V4 + q]));
    }
    float dn = g_dis[n];
    float d2 = dn * dn;
    reinterpret_cast<uint4*>(g_y1)[t] = pack8(scale4(accA, d2), scale4(accB, d2));
}

// ---- layer 2 + combine: ho = a0*x0 + a1*(y1*sqd) + a2*dis*(Σ y1[src]) ----
__global__ void k_gather_combine(const float* __restrict__ alpha) {
    int t = blockIdx.x * blockDim.x + threadIdx.x;
    if (t >= N_NODES * V4) return;
    int n = t >> 3, q = t & 7;
    int start = g_rowptr[n];
    int end = g_rowptr[n + 1];
    const uint4* y1 = reinterpret_cast<const uint4*>(g_y1);
    float4 accA = make_float4(0.f, 0.f, 0.f, 0.f);
    float4 accB = make_float4(0.f, 0.f, 0.f, 0.f);
    #pragma unroll 4
    for (int i = start; i < end; i++) {
        unsigned src = __ldg(&g_adje[i]).x;
        h8_acc(&accA, &accB, __ldg(&y1[src * V4 + q]));
    }
    float a0 = alpha[0], a1s = alpha[1] * g_sqd[n], a2d = alpha[2] * g_dis[n];
    accA = scale4(accA, a2d);
    accB = scale4(accB, a2d);
    h8_mul_acc(&accA, &accB, reinterpret_cast<const uint4*>(g_x0h)[t], a0);
    h8_mul_acc(&accA, &accB, y1[t], a1s);   // x1 = y1 * sqd
    reinterpret_cast<uint4*>(g_ho)[t] = pack8(accA, accB);
}

// ---- per-edge dots in CSR order (8-lane groups); re-zeros deg for next call --
__global__ void k_dot_csr(float* __restrict__ out) {
    int t = blockIdx.x * blockDim.x + threadIdx.x;
    if (t >= N_NODES * V4) return;
    int n = t >> 3, q = t & 7;
    int start = g_rowptr[n];
    int end = g_rowptr[n + 1];
    if (q == 0) g_deg[n] = 0;                    // maintain zero-invariant
    if (start == end) return;
    unsigned gmask = 0xFFu << (threadIdx.x & 24);
    const uint4* h = reinterpret_cast<const uint4*>(g_ho);
    uint4 uc = h[n * V4 + q];                    // dst row chunk, loop-invariant
    float2 c0 = __half22float2(*reinterpret_cast<__half2*>(&uc.x));
    float2 c1 = __half22float2(*reinterpret_cast<__half2*>(&uc.y));
    float2 c2 = __half22float2(*reinterpret_cast<__half2*>(&uc.z));
    float2 c3 = __half22float2(*reinterpret_cast<__half2*>(&uc.w));
    #pragma unroll 2
    for (int i = start; i < end; i++) {
        uint2 a = __ldg(&g_adje[i]);             // {src, eid}
        uint4 ua = __ldg(&h[a.x * V4 + q]);
        float2 s0 = __half22float2(*reinterpret_cast<__half2*>(&ua.x));
        float2 s1 = __half22float2(*reinterpret_cast<__half2*>(&ua.y));
        float2 s2 = __half22float2(*reinterpret_cast<__half2*>(&ua.z));
        float2 s3 = __half22float2(*reinterpret_cast<__half2*>(&ua.w));
        float s = s0.x * c0.x + s0.y * c0.y + s1.x * c1.x + s1.y * c1.y
                + s2.x * c2.x + s2.y * c2.y + s3.x * c3.x + s3.y * c3.y;
        s += __shfl_xor_sync(gmask, s, 4);
        s += __shfl_xor_sync(gmask, s, 2);
        s += __shfl_xor_sync(gmask, s, 1);
        if (q == 0) out[a.y] = s;
    }
}

// ---------------------------------------------------------------------------
extern "C" void kernel_launch(void* const* d_in, const int* in_sizes, int n_in,
                              void* d_out, int out_size) {
    const int*    edge_index = (const int*)d_in[0];       // [2, E]
    const int*    item_tag   = (const int*)d_in[1];
    const int*    item_testid= (const int*)d_in[2];
    const int*    item_bigcat= (const int*)d_in[3];
    const float4* user_emb   = (const float4*)d_in[4];
    const float4* item_emb   = (const float4*)d_in[5];
    const float4* tag_emb    = (const float4*)d_in[6];
    const float4* testid_emb = (const float4*)d_in[7];
    const float4* bigcat_emb = (const float4*)d_in[8];
    const float*  alpha      = (const float*)d_in[9];
    float* out = (float*)d_out;

    const int* row = edge_index;
    const int* col = edge_index + N_EDGES;
    const int B = 256;

    // degree+rank (deg pre-zeroed by static init / previous k_dot_csr)
    k_deg_rank<<<cdiv(N_EDGES, B), B>>>(col);
    k_scan_a_dis<<<NB_SCAN, 256>>>();
    // x0 features with the rowptr scan fused into its first NB_SCAN blocks
    k_x0_scan<<<cdiv(N_NODES * V4, B), B>>>(user_emb, item_emb, item_tag, item_testid,
                                            item_bigcat, tag_emb, testid_emb, bigcat_emb);
    k_fill<<<cdiv(N_EDGES, B), B>>>(row, col);

    // 2 pull layers (pre-scaled rows; second layer fused with combine)
    k_gather1<<<cdiv(N_NODES * V4, B), B>>>();
    k_gather_combine<<<cdiv(N_NODES * V4, B), B>>>(alpha);

    // per-edge dots via CSR traversal (also re-zeros deg)
    k_dot_csr<<<cdiv(N_NODES * V4, B), B>>>(out);
}

// round 16
// speedup vs baseline: 1.0241x; 1.0002x over previous
#include <cuda_runtime.h>
#include <cuda_fp16.h>

#define N_USER 100000
#define N_ITEM 20000
#define N_NODES 120000
#define N_EDGES 2000000
#define EMB 64
#define V4 8        // uint4 (8-half / 16B) chunks per 64-dim fp16 row
#define F4 16       // float4 chunks per 64-dim fp32 row
#define NB_SCAN 469 // cdiv(N_NODES, 256)

// ---- static scratch (no allocations allowed) ----
__device__ __half g_x0h[N_NODES * EMB];  // x0 (fp16)
__device__ __half g_y0[N_NODES * EMB];   // dis ⊙ x0
__device__ __half g_y1[N_NODES * EMB];   // dis ⊙ x1
__device__ __half g_ho[N_NODES * EMB];   // combined output embedding
__device__ int    g_deg[N_NODES];        // zero-initialized; re-zeroed by k_dot each call
__device__ int    g_rank[N_EDGES];       // edge's arrival rank within its dst
__device__ int    g_rowptr[N_NODES + 1];
__device__ int    g_bsum[512];
__device__ int    g_boff[512];           // exclusive prefix of g_bsum
__device__ int    g_arrive;              // scan_a completion ticket (self-resetting)
__device__ float  g_dis[N_NODES];        // 1/sqrt(deg) (0 if deg=0)
__device__ float  g_sqd[N_NODES];        // sqrt(deg)   (0 if deg=0)
__device__ uint2  g_adje[N_EDGES];       // {src, eid} grouped by dst (gather + dot)

static inline int cdiv(int a, int b) { return (a + b - 1) / b; }

__device__ __forceinline__ void h8_acc(float4* accA, float4* accB, uint4 u) {
    float2 f0 = __half22float2(*reinterpret_cast<__half2*>(&u.x));
    float2 f1 = __half22float2(*reinterpret_cast<__half2*>(&u.y));
    float2 f2 = __half22float2(*reinterpret_cast<__half2*>(&u.z));
    float2 f3 = __half22float2(*reinterpret_cast<__half2*>(&u.w));
    accA->x += f0.x; accA->y += f0.y; accA->z += f1.x; accA->w += f1.y;
    accB->x += f2.x; accB->y += f2.y; accB->z += f3.x; accB->w += f3.y;
}

__device__ __forceinline__ void h8_mul_acc(float4* accA, float4* accB, uint4 u, float s) {
    float2 f0 = __half22float2(*reinterpret_cast<__half2*>(&u.x));
    float2 f1 = __half22float2(*reinterpret_cast<__half2*>(&u.y));
    float2 f2 = __half22float2(*reinterpret_cast<__half2*>(&u.z));
    float2 f3 = __half22float2(*reinterpret_cast<__half2*>(&u.w));
    accA->x += f0.x * s; accA->y += f0.y * s; accA->z += f1.x * s; accA->w += f1.y * s;
    accB->x += f2.x * s; accB->y += f2.y * s; accB->z += f3.x * s; accB->w += f3.y * s;
}

__device__ __forceinline__ uint4 pack8(float4 a, float4 b) {
    __half2 p0 = __floats2half2_rn(a.x, a.y);
    __half2 p1 = __floats2half2_rn(a.z, a.w);
    __half2 p2 = __floats2half2_rn(b.x, b.y);
    __half2 p3 = __floats2half2_rn(b.z, b.w);
    return make_uint4(*reinterpret_cast<unsigned*>(&p0), *reinterpret_cast<unsigned*>(&p1),
                      *reinterpret_cast<unsigned*>(&p2), *reinterpret_cast<unsigned*>(&p3));
}

__device__ __forceinline__ float4 scale4(float4 v, float s) {
    return make_float4(v.x * s, v.y * s, v.z * s, v.w * s);
}

// streaming 4B store: evict-first in L2 (output is never re-read on device)
__device__ __forceinline__ void stg_cs(float* p, float v) {
    asm volatile("st.global.cs.f32 [%0], %1;" :: "l"(p), "f"(v) : "memory");
}

// ---------------------------------------------------------------------------
// degree count + per-edge rank (slot within destination) in one pass
__global__ void k_deg_rank(const int* __restrict__ col) {
    int e = blockIdx.x * blockDim.x + threadIdx.x;
    if (e < N_EDGES) g_rank[e] = atomicAdd(&g_deg[col[e]], 1);
}

// ---- block sums of deg + rsqrt/sqrt; LAST block computes g_boff prefix ----
__global__ void k_scan_a_dis() {
    __shared__ int sh[256];
    int i = blockIdx.x * 256 + threadIdx.x;
    int d = (i < N_NODES) ? g_deg[i] : 0;
    if (i < N_NODES) {
        float fd = (float)d;
        g_dis[i] = (d > 0) ? rsqrtf(fd) : 0.0f;
        g_sqd[i] = (d > 0) ? sqrtf(fd) : 0.0f;
    }
    sh[threadIdx.x] = d;
    __syncthreads();
    for (int s = 128; s > 0; s >>= 1) {
        if (threadIdx.x < s) sh[threadIdx.x] += sh[threadIdx.x + s];
        __syncthreads();
    }
    __shared__ int lastflag;
    if (threadIdx.x == 0) {
        g_bsum[blockIdx.x] = sh[0];
        __threadfence();
        lastflag = (atomicAdd(&g_arrive, 1) == gridDim.x - 1);
    }
    __syncthreads();
    if (!lastflag) return;
    // last block: exclusive prefix of g_bsum[0..NB_SCAN) into g_boff (ping-pong scan)
    __shared__ int pa[512], pb[512];
    int t = threadIdx.x;
    pa[t]       = (t < NB_SCAN) ? g_bsum[t] : 0;
    pa[t + 256] = (t + 256 < NB_SCAN) ? g_bsum[t + 256] : 0;
    __syncthreads();
    int *src = pa, *dst = pb;
    for (int off = 1; off < 512; off <<= 1) {
        dst[t]       = src[t]       + ((t >= off)       ? src[t - off]       : 0);
        dst[t + 256] = src[t + 256] + ((t + 256 >= off) ? src[t + 256 - off] : 0);
        __syncthreads();
        int* tmp = src; src = dst; dst = tmp;
    }
    if (t < NB_SCAN)       g_boff[t]       = (t == 0) ? 0 : src[t - 1];
    if (t + 256 < NB_SCAN) g_boff[t + 256] = src[t + 255];
    if (t == 0) g_arrive = 0;   // reset ticket for next call
}

// ---- x0 (fp16 + y0 = dis*x0) with rowptr scan fused into the first NB_SCAN blocks
__global__ void k_x0_scan(const float4* __restrict__ user_emb,
                          const float4* __restrict__ item_emb,
                          const int*    __restrict__ tag,
                          const int*    __restrict__ testid,
                          const int*    __restrict__ bigcat,
                          const float4* __restrict__ tag_emb,
                          const float4* __restrict__ testid_emb,
                          const float4* __restrict__ bigcat_emb) {
    // part 1: rowptr (exclusive, N+1) for blocks < NB_SCAN
    if (blockIdx.x < NB_SCAN) {
        __shared__ int sh[256];
        int i = blockIdx.x * 256 + threadIdx.x;
        int v = (i < N_NODES) ? g_deg[i] : 0;
        sh[threadIdx.x] = v;
        __syncthreads();
        for (int off = 1; off < 256; off <<= 1) {
            int x = (threadIdx.x >= off) ? sh[threadIdx.x - off] : 0;
            __syncthreads();
            sh[threadIdx.x] += x;
            __syncthreads();
        }
        if (i < N_NODES) {
            g_rowptr[i + 1] = g_boff[blockIdx.x] + sh[threadIdx.x];
            if (i == 0) g_rowptr[0] = 0;
        }
    }
    // part 2: x0 features (all blocks)
    int t = blockIdx.x * blockDim.x + threadIdx.x;
    if (t >= N_NODES * V4) return;
    int n = t >> 3, q = t & 7;
    float4 va, vb;
    if (n < N_USER) {
        va = user_emb[n * F4 + 2 * q];
        vb = user_emb[n * F4 + 2 * q + 1];
    } else {
        int i = n - N_USER;
        int tg = tag[i] * F4, ts = testid[i] * F4, bc = bigcat[i] * F4;
        float4 a0 = item_emb[i * F4 + 2 * q],     a1 = item_emb[i * F4 + 2 * q + 1];
        float4 b0 = tag_emb[tg + 2 * q],          b1 = tag_emb[tg + 2 * q + 1];
        float4 c0 = testid_emb[ts + 2 * q],       c1 = testid_emb[ts + 2 * q + 1];
        float4 d0 = bigcat_emb[bc + 2 * q],       d1 = bigcat_emb[bc + 2 * q + 1];
        va = make_float4((a0.x + b0.x + c0.x + d0.x) * 0.25f,
                         (a0.y + b0.y + c0.y + d0.y) * 0.25f,
                         (a0.z + b0.z + c0.z + d0.z) * 0.25f,
                         (a0.w + b0.w + c0.w + d0.w) * 0.25f);
        vb = make_float4((a1.x + b1.x + c1.x + d1.x) * 0.25f,
                         (a1.y + b1.y + c1.y + d1.y) * 0.25f,
                         (a1.z + b1.z + c1.z + d1.z) * 0.25f,
                         (a1.w + b1.w + c1.w + d1.w) * 0.25f);
    }
    float dn = g_dis[n];
    reinterpret_cast<uint4*>(g_x0h)[t] = pack8(va, vb);
    reinterpret_cast<uint4*>(g_y0)[t]  = pack8(scale4(va, dn), scale4(vb, dn));
}

// ---- CSR fill: atomic-free; slot = rowptr[dst] + rank ----
__global__ void k_fill(const int* __restrict__ row, const int* __restrict__ col) {
    int e = blockIdx.x * blockDim.x + threadIdx.x;
    if (e >= N_EDGES) return;
    int r = row[e], c = col[e];
    int pos = __ldg(&g_rowptr[c]) + g_rank[e];
    g_adje[pos] = make_uint2((unsigned)r, (unsigned)e);
}

// ---- layer 1: acc = Σ y0[src]; y1 = dis²*acc (x1 recovered as y1*sqd later) --
__global__ void k_gather1() {
    int t = blockIdx.x * blockDim.x + threadIdx.x;
    if (t >= N_NODES * V4) return;
    int n = t >> 3, q = t & 7;
    int start = g_rowptr[n];
    int end = g_rowptr[n + 1];
    const uint4* y0 = reinterpret_cast<const uint4*>(g_y0);
    float4 accA = make_float4(0.f, 0.f, 0.f, 0.f);
    float4 accB = make_float4(0.f, 0.f, 0.f, 0.f);
    #pragma unroll 4
    for (int i = start; i < end; i++) {
        unsigned src = __ldg(&g_adje[i]).x;
        h8_acc(&accA, &accB, __ldg(&y0[src * V4 + q]));
    }
    float dn = g_dis[n];
    float d2 = dn * dn;
    reinterpret_cast<uint4*>(g_y1)[t] = pack8(scale4(accA, d2), scale4(accB, d2));
}

// ---- layer 2 + combine: ho = a0*x0 + a1*(y1*sqd) + a2*dis*(Σ y1[src]) ----
__global__ void k_gather_combine(const float* __restrict__ alpha) {
    int t = blockIdx.x * blockDim.x + threadIdx.x;
    if (t >= N_NODES * V4) return;
    int n = t >> 3, q = t & 7;
    int start = g_rowptr[n];
    int end = g_rowptr[n + 1];
    const uint4* y1 = reinterpret_cast<const uint4*>(g_y1);
    float4 accA = make_float4(0.f, 0.f, 0.f, 0.f);
    float4 accB = make_float4(0.f, 0.f, 0.f, 0.f);
    #pragma unroll 4
    for (int i = start; i < end; i++) {
        unsigned src = __ldg(&g_adje[i]).x;
        h8_acc(&accA, &accB, __ldg(&y1[src * V4 + q]));
    }
    float a0 = alpha[0], a1s = alpha[1] * g_sqd[n], a2d = alpha[2] * g_dis[n];
    accA = scale4(accA, a2d);
    accB = scale4(accB, a2d);
    h8_mul_acc(&accA, &accB, reinterpret_cast<const uint4*>(g_x0h)[t], a0);
    h8_mul_acc(&accA, &accB, y1[t], a1s);   // x1 = y1 * sqd
    reinterpret_cast<uint4*>(g_ho)[t] = pack8(accA, accB);
}

// ---- per-edge dots in CSR order (8-lane groups); streaming out stores;
//      re-zeros deg for next call ----
__global__ void k_dot_csr(float* __restrict__ out) {
    int t = blockIdx.x * blockDim.x + threadIdx.x;
    if (t >= N_NODES * V4) return;
    int n = t >> 3, q = t & 7;
    int start = g_rowptr[n];
    int end = g_rowptr[n + 1];
    if (q == 0) g_deg[n] = 0;                    // maintain zero-invariant
    if (start == end) return;
    unsigned gmask = 0xFFu << (threadIdx.x & 24);
    const uint4* h = reinterpret_cast<const uint4*>(g_ho);
    uint4 uc = h[n * V4 + q];                    // dst row chunk, loop-invariant
    float2 c0 = __half22float2(*reinterpret_cast<__half2*>(&uc.x));
    float2 c1 = __half22float2(*reinterpret_cast<__half2*>(&uc.y));
    float2 c2 = __half22float2(*reinterpret_cast<__half2*>(&uc.z));
    float2 c3 = __half22float2(*reinterpret_cast<__half2*>(&uc.w));
    #pragma unroll 2
    for (int i = start; i < end; i++) {
        uint2 a = __ldg(&g_adje[i]);             // {src, eid}
        uint4 ua = __ldg(&h[a.x * V4 + q]);
        float2 s0 = __half22float2(*reinterpret_cast<__half2*>(&ua.x));
        float2 s1 = __half22float2(*reinterpret_cast<__half2*>(&ua.y));
        float2 s2 = __half22float2(*reinterpret_cast<__half2*>(&ua.z));
        float2 s3 = __half22float2(*reinterpret_cast<__half2*>(&ua.w));
        float s = s0.x * c0.x + s0.y * c0.y + s1.x * c1.x + s1.y * c1.y
                + s2.x * c2.x + s2.y * c2.y + s3.x * c3.x + s3.y * c3.y;
        s += __shfl_xor_sync(gmask, s, 4);
        s += __shfl_xor_sync(gmask, s, 2);
        s += __shfl_xor_sync(gmask, s, 1);
        if (q == 0) stg_cs(&out[a.y], s);        // evict-first: never re-read
    }
}

// ---------------------------------------------------------------------------
extern "C" void kernel_launch(void* const* d_in, const int* in_sizes, int n_in,
                              void* d_out, int out_size) {
    const int*    edge_index = (const int*)d_in[0];       // [2, E]
    const int*    item_tag   = (const int*)d_in[1];
    const int*    item_testid= (const int*)d_in[2];
    const int*    item_bigcat= (const int*)d_in[3];
    const float4* user_emb   = (const float4*)d_in[4];
    const float4* item_emb   = (const float4*)d_in[5];
    const float4* tag_emb    = (const float4*)d_in[6];
    const float4* testid_emb = (const float4*)d_in[7];
    const float4* bigcat_emb = (const float4*)d_in[8];
    const float*  alpha      = (const float*)d_in[9];
    float* out = (float*)d_out;

    const int* row = edge_index;
    const int* col = edge_index + N_EDGES;
    const int B = 256;

    // degree+rank (deg pre-zeroed by static init / previous k_dot_csr)
    k_deg_rank<<<cdiv(N_EDGES, B), B>>>(col);
    k_scan_a_dis<<<NB_SCAN, 256>>>();
    // x0 features with the rowptr scan fused into its first NB_SCAN blocks
    k_x0_scan<<<cdiv(N_NODES * V4, B), B>>>(user_emb, item_emb, item_tag, item_testid,
                                            item_bigcat, tag_emb, testid_emb, bigcat_emb);
    k_fill<<<cdiv(N_EDGES, B), B>>>(row, col);

    // 2 pull layers (pre-scaled rows; second layer fused with combine)
    k_gather1<<<cdiv(N_NODES * V4, B), B>>>();
    k_gather_combine<<<cdiv(N_NODES * V4, B), B>>>(alpha);

    // per-edge dots via CSR traversal (also re-zeros deg)
    k_dot_csr<<<cdiv(N_NODES * V4, B), B>>>(out);
}